// round 8
// baseline (speedup 1.0000x reference)
#include <cuda_runtime.h>

#define IMG_H 512
#define IMG_W 512
#define OUT_H 502
#define OUT_W 502
#define NIMG 32
#define HALO 10
#define STRIP 28          // output rows per block (18 strips: 17x28 + 26)
#define NSTRIPS 18
#define NTHREADS 256
#define NBLOCKS (NSTRIPS * NIMG)   // 576 = 97.3% of 2 full waves at occ 2
#define NCP 266           // column-pairs per smem row (264 used + pad)

__device__ float g_partial[NBLOCKS * 2];
__device__ unsigned g_count = 0;

// ---- packed f32x2 helpers (ptxas never fuses these from C++) ----
typedef unsigned long long u64t;
__device__ __forceinline__ u64t pk2(float lo, float hi) {
    u64t r; asm("mov.b64 %0, {%1,%2};" : "=l"(r) : "f"(lo), "f"(hi)); return r;
}
__device__ __forceinline__ void upk2(u64t v, float& lo, float& hi) {
    asm("mov.b64 {%0,%1}, %2;" : "=f"(lo), "=f"(hi) : "l"(v));
}
__device__ __forceinline__ u64t fma2(u64t a, u64t b, u64t c) {
    u64t d; asm("fma.rn.f32x2 %0, %1, %2, %3;" : "=l"(d) : "l"(a), "l"(b), "l"(c)); return d;
}
__device__ __forceinline__ u64t mul2(u64t a, u64t b) {
    u64t d; asm("mul.rn.f32x2 %0, %1, %2;" : "=l"(d) : "l"(a), "l"(b)); return d;
}

// Horizontal 11-tap blur for 2 adjacent output cols, TWO channels at once from
// a pair-interleaved float4 row: q = (chA_even, chB_even, chA_odd, chB_odd).
// 6 LDS.128 serve both channels (was 12 LDS.64).
__device__ __forceinline__ void hblur2(const float4* __restrict__ row, int tid,
                                       const u64t* __restrict__ GWP,
                                       u64t& hA, u64t& hB)
{
    float4 q[6];
#pragma unroll
    for (int m = 0; m < 6; ++m) q[m] = row[tid + m];
    hA = mul2(GWP[0], pk2(q[0].x, q[0].z));
    hB = mul2(GWP[0], pk2(q[0].y, q[0].w));
#pragma unroll
    for (int k = 1; k < 11; ++k) {
        const int m = k >> 1;
        u64t PA = (k & 1) ? pk2(q[m].z, q[m + 1].x) : pk2(q[m].x, q[m].z);
        u64t PB = (k & 1) ? pk2(q[m].w, q[m + 1].y) : pk2(q[m].y, q[m].w);
        hA = fma2(GWP[k], PA, hA);
        hB = fma2(GWP[k], PB, hB);
    }
}

__global__ __launch_bounds__(NTHREADS, 2)
void fused_mse_ssim(const float* __restrict__ pred, const float* __restrict__ targ,
                    float* __restrict__ out)
{
    const float GW[11] = {
        0.00102838f, 0.00759876f, 0.03600077f, 0.10936070f, 0.21300554f,
        0.26601172f,
        0.21300554f, 0.10936070f, 0.03600077f, 0.00759876f, 0.00102838f
    };
    u64t GWP[11];
#pragma unroll
    for (int k = 0; k < 11; ++k) GWP[k] = pk2(GW[k], GW[k]);
    const float C1 = 1e-4f, C2 = 9e-4f;

    // Pair-interleaved channel rows, double-buffered by pair parity, 2 rows/pair.
    // sPT[par][row][cp] = (p0, t0, p1, t1) ; sSD[par][row][cp] = (ss0, dd0, ss1, dd1)
    __shared__ float4 sPT[2][2][NCP];
    __shared__ float4 sSD[2][2][NCP];
    __shared__ float red_m[8], red_s[8];
    __shared__ unsigned s_ticket;

    const int tid = threadIdx.x;
    const int y0  = blockIdx.x * STRIP;
    const int img = blockIdx.y;

    const int n_out    = min(STRIP, OUT_H - y0);    // 28 or 26
    const int n_in     = n_out + HALO;              // 38 or 36 (always even)
    const int mse_rows = min(IMG_H - y0, (blockIdx.x == NSTRIPS - 1) ? 999 : STRIP);

    const float* __restrict__ pbase = pred + (size_t)img * (IMG_H * IMG_W);
    const float* __restrict__ tbase = targ + (size_t)img * (IMG_H * IMG_W);

    // Vertical streaming accumulators: 11 slots x 4 ch (M1,M2,BS,BD), col-pair packed
    u64t acc[11][4];
#pragma unroll
    for (int sl = 0; sl < 11; ++sl)
#pragma unroll
        for (int c = 0; c < 4; ++c) acc[sl][c] = 0ull;

    float mse_acc = 0.f, ssim_acc = 0.f;
    const bool emit_col = (tid <= 250);

    // Preload rows 0 and 1
    float2 pp0 = ((const float2*)(pbase + (size_t)(y0 + 0) * IMG_W))[tid];
    float2 tt0 = ((const float2*)(tbase + (size_t)(y0 + 0) * IMG_W))[tid];
    float2 pp1 = ((const float2*)(pbase + (size_t)(y0 + 1) * IMG_W))[tid];
    float2 tt1 = ((const float2*)(tbase + (size_t)(y0 + 1) * IMG_W))[tid];

    for (int rb = 0; rb < 44; rb += 22) {          // 22 rows ≡ 0 (mod 11)
#pragma unroll
        for (int pj = 0; pj < 11; ++pj) {
            const int r0 = rb + 2 * pj;            // even row of pair
            const int r1 = r0 + 1;
            const int j0 = (2 * pj) % 11;          // static slot indices
            const int j1 = (2 * pj + 1) % 11;
            if (r0 < n_in) {                       // block-uniform
                const bool has1 = (r1 < n_in);     // block-uniform
                const int par2 = (r0 >> 1) & 1;

                // ---- channel prep + MSE + STS.128 for both rows ----
                {
                    float d0 = pp0.x - tt0.x, s0 = pp0.x + tt0.x;
                    float d1 = pp0.y - tt0.y, s1 = pp0.y + tt0.y;
                    if (r0 < mse_rows) {
                        mse_acc = fmaf(d0, d0, mse_acc);
                        mse_acc = fmaf(d1, d1, mse_acc);
                    }
                    sPT[par2][0][tid] = make_float4(pp0.x, tt0.x, pp0.y, tt0.y);
                    sSD[par2][0][tid] = make_float4(s0 * s0, d0 * d0, s1 * s1, d1 * d1);
                }
                if (has1) {
                    float d0 = pp1.x - tt1.x, s0 = pp1.x + tt1.x;
                    float d1 = pp1.y - tt1.y, s1 = pp1.y + tt1.y;
                    if (r1 < mse_rows) {
                        mse_acc = fmaf(d0, d0, mse_acc);
                        mse_acc = fmaf(d1, d1, mse_acc);
                    }
                    sPT[par2][1][tid] = make_float4(pp1.x, tt1.x, pp1.y, tt1.y);
                    sSD[par2][1][tid] = make_float4(s0 * s0, d0 * d0, s1 * s1, d1 * d1);
                }

                // ---- prefetch next pair (hide LDG latency across barrier) ----
                if (r0 + 2 < n_in) {
                    const size_t off = (size_t)(y0 + r0 + 2) * IMG_W;
                    pp0 = ((const float2*)(pbase + off))[tid];
                    tt0 = ((const float2*)(tbase + off))[tid];
                }
                if (r1 + 2 < n_in) {
                    const size_t off = (size_t)(y0 + r1 + 2) * IMG_W;
                    pp1 = ((const float2*)(pbase + off))[tid];
                    tt1 = ((const float2*)(tbase + off))[tid];
                }
                __syncthreads();

                // ---- row0: horizontal blur + vertical streaming + emit ----
                {
                    u64t hv[4];
                    hblur2(sPT[par2][0], tid, GWP, hv[0], hv[1]);   // M1, M2
                    hblur2(sSD[par2][0], tid, GWP, hv[2], hv[3]);   // BS, BD
#pragma unroll
                    for (int c = 0; c < 4; ++c) acc[j0][c] = mul2(GWP[0], hv[c]);
#pragma unroll
                    for (int d = 1; d < 11; ++d) {
                        const int sl = (j0 - d + 11) % 11;
#pragma unroll
                        for (int c = 0; c < 4; ++c)
                            acc[sl][c] = fma2(GWP[d], hv[c], acc[sl][c]);
                    }
                    if (r0 >= HALO && emit_col) {
                        const int es = (j0 + 1) % 11;
                        float M1[2], M2[2], BS[2], BD[2];
                        upk2(acc[es][0], M1[0], M1[1]);
                        upk2(acc[es][1], M2[0], M2[1]);
                        upk2(acc[es][2], BS[0], BS[1]);
                        upk2(acc[es][3], BD[0], BD[1]);
#pragma unroll
                        for (int col = 0; col < 2; ++col) {
                            float m1s = M1[col] * M1[col];
                            float m2s = M2[col] * M2[col];
                            float m12 = M1[col] * M2[col];
                            float sums = m1s + m2s;
                            float sigsum = fmaf(0.5f,  BS[col] + BD[col], -sums);
                            float sig12  = fmaf(0.25f, BS[col] - BD[col], -m12);
                            float num = (2.f * m12 + C1) * (2.f * sig12 + C2);
                            float den = fmaf(sums + C1, sigsum + C2, 1e-6f);
                            ssim_acc += __fdividef(num, den);
                        }
                    }
                }

                // ---- row1 ----
                if (has1) {
                    u64t hv[4];
                    hblur2(sPT[par2][1], tid, GWP, hv[0], hv[1]);
                    hblur2(sSD[par2][1], tid, GWP, hv[2], hv[3]);
#pragma unroll
                    for (int c = 0; c < 4; ++c) acc[j1][c] = mul2(GWP[0], hv[c]);
#pragma unroll
                    for (int d = 1; d < 11; ++d) {
                        const int sl = (j1 - d + 11) % 11;
#pragma unroll
                        for (int c = 0; c < 4; ++c)
                            acc[sl][c] = fma2(GWP[d], hv[c], acc[sl][c]);
                    }
                    if (r1 >= HALO && emit_col) {
                        const int es = (j1 + 1) % 11;
                        float M1[2], M2[2], BS[2], BD[2];
                        upk2(acc[es][0], M1[0], M1[1]);
                        upk2(acc[es][1], M2[0], M2[1]);
                        upk2(acc[es][2], BS[0], BS[1]);
                        upk2(acc[es][3], BD[0], BD[1]);
#pragma unroll
                        for (int col = 0; col < 2; ++col) {
                            float m1s = M1[col] * M1[col];
                            float m2s = M2[col] * M2[col];
                            float m12 = M1[col] * M2[col];
                            float sums = m1s + m2s;
                            float sigsum = fmaf(0.5f,  BS[col] + BD[col], -sums);
                            float sig12  = fmaf(0.25f, BS[col] - BD[col], -m12);
                            float num = (2.f * m12 + C1) * (2.f * sig12 + C2);
                            float den = fmaf(sums + C1, sigsum + C2, 1e-6f);
                            ssim_acc += __fdividef(num, den);
                        }
                    }
                }
            }
        }
    }

    // Block reduction
#pragma unroll
    for (int off = 16; off > 0; off >>= 1) {
        mse_acc  += __shfl_down_sync(0xffffffffu, mse_acc,  off);
        ssim_acc += __shfl_down_sync(0xffffffffu, ssim_acc, off);
    }
    const int wrp = tid >> 5, lane = tid & 31;
    if (lane == 0) { red_m[wrp] = mse_acc; red_s[wrp] = ssim_acc; }
    __syncthreads();
    if (tid == 0) {
        float m = 0.f, s = 0.f;
#pragma unroll
        for (int w = 0; w < 8; ++w) { m += red_m[w]; s += red_s[w]; }
        const int bid = blockIdx.y * NSTRIPS + blockIdx.x;
        g_partial[bid * 2 + 0] = m;
        g_partial[bid * 2 + 1] = s;
        __threadfence();
        s_ticket = atomicAdd(&g_count, 1u);
    }
    __syncthreads();

    // Last block folds in the final reduction (no 2nd launch)
    if (s_ticket == NBLOCKS - 1) {
        __threadfence();
        double m = 0.0, s = 0.0;
        for (int i = tid; i < NBLOCKS; i += NTHREADS) {
            m += (double)g_partial[i * 2 + 0];
            s += (double)g_partial[i * 2 + 1];
        }
#pragma unroll
        for (int off = 16; off > 0; off >>= 1) {
            m += __shfl_down_sync(0xffffffffu, m, off);
            s += __shfl_down_sync(0xffffffffu, s, off);
        }
        __shared__ double sm[8], ss[8];
        if (lane == 0) { sm[wrp] = m; ss[wrp] = s; }
        __syncthreads();
        if (tid == 0) {
            double M = 0.0, S = 0.0;
#pragma unroll
            for (int w = 0; w < 8; ++w) { M += sm[w]; S += ss[w]; }
            const double mse_n  = (double)NIMG * IMG_H * IMG_W;
            const double ssim_n = (double)NIMG * OUT_H * OUT_W;
            double mse_loss  = M / mse_n;
            double ssim_loss = 1.0 - S / ssim_n;
            out[0] = (float)(0.6 * mse_loss + 0.4 * ssim_loss);
            g_count = 0;   // self-reset for next graph replay
        }
    }
}

extern "C" void kernel_launch(void* const* d_in, const int* in_sizes, int n_in,
                              void* d_out, int out_size)
{
    const float* pred = (const float*)d_in[0];
    const float* targ = (const float*)d_in[1];

    dim3 grid(NSTRIPS, NIMG, 1);   // 18 x 32 = 576 blocks
    fused_mse_ssim<<<grid, NTHREADS>>>(pred, targ, (float*)d_out);
}

// round 10
// speedup vs baseline: 1.0315x; 1.0315x over previous
#include <cuda_runtime.h>

#define IMG_H 512
#define IMG_W 512
#define OUT_H 502
#define OUT_W 502
#define NIMG 32
#define HALO 10
#define STRIP 28          // output rows per block (18 strips: 17x28 + 26)
#define NSTRIPS 18
#define NTHREADS 256
#define NBLOCKS (NSTRIPS * NIMG)   // 576 = 97.3% of 2 full waves at occ 2
#define NCP 266           // column-pairs per smem row (264 used + pad)

__device__ float g_partial[NBLOCKS * 2];
__device__ unsigned g_count = 0;

// ---- packed f32x2 helpers (ptxas never fuses these from C++) ----
typedef unsigned long long u64t;
__device__ __forceinline__ u64t pk2(float lo, float hi) {
    u64t r; asm("mov.b64 %0, {%1,%2};" : "=l"(r) : "f"(lo), "f"(hi)); return r;
}
__device__ __forceinline__ void upk2(u64t v, float& lo, float& hi) {
    asm("mov.b64 {%0,%1}, %2;" : "=f"(lo), "=f"(hi) : "l"(v));
}
__device__ __forceinline__ u64t fma2(u64t a, u64t b, u64t c) {
    u64t d; asm("fma.rn.f32x2 %0, %1, %2, %3;" : "=l"(d) : "l"(a), "l"(b), "l"(c)); return d;
}
__device__ __forceinline__ u64t mul2(u64t a, u64t b) {
    u64t d; asm("mul.rn.f32x2 %0, %1, %2;" : "=l"(d) : "l"(a), "l"(b)); return d;
}

// Horizontal 11-tap blur for 2 adjacent output cols, TWO channels at once.
// Layout per column-pair: q = (A_even, A_odd, B_even, B_odd) -> even-k packs
// are ADJACENT register pairs from the LDS.128 (fold to free 64-bit views);
// only the 5 odd-k packs per channel are real MOVs.
__device__ __forceinline__ void hblur2(const float4* __restrict__ row, int tid,
                                       const u64t* __restrict__ GWP,
                                       u64t& hA, u64t& hB)
{
    float4 q[6];
#pragma unroll
    for (int m = 0; m < 6; ++m) q[m] = row[tid + m];
    hA = mul2(GWP[0], pk2(q[0].x, q[0].y));   // adjacent -> free pack
    hB = mul2(GWP[0], pk2(q[0].z, q[0].w));   // adjacent -> free pack
#pragma unroll
    for (int k = 1; k < 11; ++k) {
        const int m = k >> 1;
        u64t PA = (k & 1) ? pk2(q[m].y, q[m + 1].x) : pk2(q[m].x, q[m].y);
        u64t PB = (k & 1) ? pk2(q[m].w, q[m + 1].z) : pk2(q[m].z, q[m].w);
        hA = fma2(GWP[k], PA, hA);
        hB = fma2(GWP[k], PB, hB);
    }
}

__global__ __launch_bounds__(NTHREADS, 2)
void fused_mse_ssim(const float* __restrict__ pred, const float* __restrict__ targ,
                    float* __restrict__ out)
{
    const float GW[11] = {
        0.00102838f, 0.00759876f, 0.03600077f, 0.10936070f, 0.21300554f,
        0.26601172f,
        0.21300554f, 0.10936070f, 0.03600077f, 0.00759876f, 0.00102838f
    };
    u64t GWP[11];
#pragma unroll
    for (int k = 0; k < 11; ++k) GWP[k] = pk2(GW[k], GW[k]);
    const float C1 = 1e-4f, C2 = 9e-4f;

    // Pair-interleaved channel rows, double-buffered by pair parity, 2 rows/pair.
    // sPT[par][row][cp] = (p0, p1, t0, t1) ; sSD[par][row][cp] = (ss0, ss1, dd0, dd1)
    __shared__ float4 sPT[2][2][NCP];
    __shared__ float4 sSD[2][2][NCP];
    __shared__ float red_m[8], red_s[8];
    __shared__ unsigned s_ticket;

    const int tid = threadIdx.x;
    const int y0  = blockIdx.x * STRIP;
    const int img = blockIdx.y;

    const int n_out    = min(STRIP, OUT_H - y0);    // 28 or 26
    const int n_in     = n_out + HALO;              // 38 or 36 (always even)
    const int mse_rows = min(IMG_H - y0, (blockIdx.x == NSTRIPS - 1) ? 999 : STRIP);

    const float* __restrict__ pbase = pred + (size_t)img * (IMG_H * IMG_W);
    const float* __restrict__ tbase = targ + (size_t)img * (IMG_H * IMG_W);

    // Vertical streaming accumulators: 11 slots x 4 ch (M1,M2,BS,BD), col-pair packed
    u64t acc[11][4];
#pragma unroll
    for (int sl = 0; sl < 11; ++sl)
#pragma unroll
        for (int c = 0; c < 4; ++c) acc[sl][c] = 0ull;

    float mse_acc = 0.f, ssim_acc = 0.f;
    const bool emit_col = (tid <= 250);

    // Preload rows 0 and 1
    float2 pp0 = ((const float2*)(pbase + (size_t)(y0 + 0) * IMG_W))[tid];
    float2 tt0 = ((const float2*)(tbase + (size_t)(y0 + 0) * IMG_W))[tid];
    float2 pp1 = ((const float2*)(pbase + (size_t)(y0 + 1) * IMG_W))[tid];
    float2 tt1 = ((const float2*)(tbase + (size_t)(y0 + 1) * IMG_W))[tid];

    for (int rb = 0; rb < 44; rb += 22) {          // 22 rows ≡ 0 (mod 11)
#pragma unroll
        for (int pj = 0; pj < 11; ++pj) {
            const int r0 = rb + 2 * pj;            // even row of pair
            const int r1 = r0 + 1;
            const int j0 = (2 * pj) % 11;          // static slot indices
            const int j1 = (2 * pj + 1) % 11;
            if (r0 < n_in) {                       // block-uniform
                const bool has1 = (r1 < n_in);     // block-uniform
                const int par2 = (r0 >> 1) & 1;

                // ---- channel prep + MSE + STS.128 for both rows ----
                {
                    float d0 = pp0.x - tt0.x, s0 = pp0.x + tt0.x;
                    float d1 = pp0.y - tt0.y, s1 = pp0.y + tt0.y;
                    if (r0 < mse_rows) {
                        mse_acc = fmaf(d0, d0, mse_acc);
                        mse_acc = fmaf(d1, d1, mse_acc);
                    }
                    sPT[par2][0][tid] = make_float4(pp0.x, pp0.y, tt0.x, tt0.y);
                    sSD[par2][0][tid] = make_float4(s0 * s0, s1 * s1, d0 * d0, d1 * d1);
                }
                if (has1) {
                    float d0 = pp1.x - tt1.x, s0 = pp1.x + tt1.x;
                    float d1 = pp1.y - tt1.y, s1 = pp1.y + tt1.y;
                    if (r1 < mse_rows) {
                        mse_acc = fmaf(d0, d0, mse_acc);
                        mse_acc = fmaf(d1, d1, mse_acc);
                    }
                    sPT[par2][1][tid] = make_float4(pp1.x, pp1.y, tt1.x, tt1.y);
                    sSD[par2][1][tid] = make_float4(s0 * s0, s1 * s1, d0 * d0, d1 * d1);
                }

                // ---- prefetch next pair (hide LDG latency across barrier) ----
                if (r0 + 2 < n_in) {
                    const size_t off = (size_t)(y0 + r0 + 2) * IMG_W;
                    pp0 = ((const float2*)(pbase + off))[tid];
                    tt0 = ((const float2*)(tbase + off))[tid];
                }
                if (r1 + 2 < n_in) {
                    const size_t off = (size_t)(y0 + r1 + 2) * IMG_W;
                    pp1 = ((const float2*)(pbase + off))[tid];
                    tt1 = ((const float2*)(tbase + off))[tid];
                }
                __syncthreads();

                // ---- row0: horizontal blur + vertical streaming + emit ----
                {
                    u64t hv[4];
                    hblur2(sPT[par2][0], tid, GWP, hv[0], hv[1]);   // M1, M2
                    hblur2(sSD[par2][0], tid, GWP, hv[2], hv[3]);   // BS, BD
#pragma unroll
                    for (int c = 0; c < 4; ++c) acc[j0][c] = mul2(GWP[0], hv[c]);
#pragma unroll
                    for (int d = 1; d < 11; ++d) {
                        const int sl = (j0 - d + 11) % 11;
#pragma unroll
                        for (int c = 0; c < 4; ++c)
                            acc[sl][c] = fma2(GWP[d], hv[c], acc[sl][c]);
                    }
                    if (r0 >= HALO && emit_col) {
                        const int es = (j0 + 1) % 11;
                        float M1[2], M2[2], BS[2], BD[2];
                        upk2(acc[es][0], M1[0], M1[1]);
                        upk2(acc[es][1], M2[0], M2[1]);
                        upk2(acc[es][2], BS[0], BS[1]);
                        upk2(acc[es][3], BD[0], BD[1]);
#pragma unroll
                        for (int col = 0; col < 2; ++col) {
                            float m1s = M1[col] * M1[col];
                            float m2s = M2[col] * M2[col];
                            float m12 = M1[col] * M2[col];
                            float sums = m1s + m2s;
                            float sigsum = fmaf(0.5f,  BS[col] + BD[col], -sums);
                            float sig12  = fmaf(0.25f, BS[col] - BD[col], -m12);
                            float num = (2.f * m12 + C1) * (2.f * sig12 + C2);
                            float den = fmaf(sums + C1, sigsum + C2, 1e-6f);
                            ssim_acc += __fdividef(num, den);
                        }
                    }
                }

                // ---- row1 ----
                if (has1) {
                    u64t hv[4];
                    hblur2(sPT[par2][1], tid, GWP, hv[0], hv[1]);
                    hblur2(sSD[par2][1], tid, GWP, hv[2], hv[3]);
#pragma unroll
                    for (int c = 0; c < 4; ++c) acc[j1][c] = mul2(GWP[0], hv[c]);
#pragma unroll
                    for (int d = 1; d < 11; ++d) {
                        const int sl = (j1 - d + 11) % 11;
#pragma unroll
                        for (int c = 0; c < 4; ++c)
                            acc[sl][c] = fma2(GWP[d], hv[c], acc[sl][c]);
                    }
                    if (r1 >= HALO && emit_col) {
                        const int es = (j1 + 1) % 11;
                        float M1[2], M2[2], BS[2], BD[2];
                        upk2(acc[es][0], M1[0], M1[1]);
                        upk2(acc[es][1], M2[0], M2[1]);
                        upk2(acc[es][2], BS[0], BS[1]);
                        upk2(acc[es][3], BD[0], BD[1]);
#pragma unroll
                        for (int col = 0; col < 2; ++col) {
                            float m1s = M1[col] * M1[col];
                            float m2s = M2[col] * M2[col];
                            float m12 = M1[col] * M2[col];
                            float sums = m1s + m2s;
                            float sigsum = fmaf(0.5f,  BS[col] + BD[col], -sums);
                            float sig12  = fmaf(0.25f, BS[col] - BD[col], -m12);
                            float num = (2.f * m12 + C1) * (2.f * sig12 + C2);
                            float den = fmaf(sums + C1, sigsum + C2, 1e-6f);
                            ssim_acc += __fdividef(num, den);
                        }
                    }
                }
            }
        }
    }

    // Block reduction
#pragma unroll
    for (int off = 16; off > 0; off >>= 1) {
        mse_acc  += __shfl_down_sync(0xffffffffu, mse_acc,  off);
        ssim_acc += __shfl_down_sync(0xffffffffu, ssim_acc, off);
    }
    const int wrp = tid >> 5, lane = tid & 31;
    if (lane == 0) { red_m[wrp] = mse_acc; red_s[wrp] = ssim_acc; }
    __syncthreads();
    if (tid == 0) {
        float m = 0.f, s = 0.f;
#pragma unroll
        for (int w = 0; w < 8; ++w) { m += red_m[w]; s += red_s[w]; }
        const int bid = blockIdx.y * NSTRIPS + blockIdx.x;
        g_partial[bid * 2 + 0] = m;
        g_partial[bid * 2 + 1] = s;
        __threadfence();
        s_ticket = atomicAdd(&g_count, 1u);
    }
    __syncthreads();

    // Last block folds in the final reduction (no 2nd launch)
    if (s_ticket == NBLOCKS - 1) {
        __threadfence();
        double m = 0.0, s = 0.0;
        for (int i = tid; i < NBLOCKS; i += NTHREADS) {
            m += (double)g_partial[i * 2 + 0];
            s += (double)g_partial[i * 2 + 1];
        }
#pragma unroll
        for (int off = 16; off > 0; off >>= 1) {
            m += __shfl_down_sync(0xffffffffu, m, off);
            s += __shfl_down_sync(0xffffffffu, s, off);
        }
        __shared__ double sm[8], ss[8];
        if (lane == 0) { sm[wrp] = m; ss[wrp] = s; }
        __syncthreads();
        if (tid == 0) {
            double M = 0.0, S = 0.0;
#pragma unroll
            for (int w = 0; w < 8; ++w) { M += sm[w]; S += ss[w]; }
            const double mse_n  = (double)NIMG * IMG_H * IMG_W;
            const double ssim_n = (double)NIMG * OUT_H * OUT_W;
            double mse_loss  = M / mse_n;
            double ssim_loss = 1.0 - S / ssim_n;
            out[0] = (float)(0.6 * mse_loss + 0.4 * ssim_loss);
            g_count = 0;   // self-reset for next graph replay
        }
    }
}

extern "C" void kernel_launch(void* const* d_in, const int* in_sizes, int n_in,
                              void* d_out, int out_size)
{
    const float* pred = (const float*)d_in[0];
    const float* targ = (const float*)d_in[1];

    dim3 grid(NSTRIPS, NIMG, 1);   // 18 x 32 = 576 blocks
    fused_mse_ssim<<<grid, NTHREADS>>>(pred, targ, (float*)d_out);
}

// round 12
// speedup vs baseline: 1.2532x; 1.2150x over previous
#include <cuda_runtime.h>

#define IMG_H 512
#define IMG_W 512
#define OUT_H 502
#define OUT_W 502
#define NIMG 32
#define HALO 10
#define STRIP 28          // output rows per block (18 strips: 17x28 + 26)
#define NSTRIPS 18
#define NTHREADS 256
#define NBLOCKS (NSTRIPS * NIMG)   // 576 = 97.3% of 2 full waves at occ 2
#define NCP 266           // column-pairs per smem row (264 used + pad)

__device__ float g_partial[NBLOCKS * 2];
__device__ unsigned g_count = 0;

// ---- packed f32x2 helpers (ptxas never fuses these from C++) ----
typedef unsigned long long u64t;
__device__ __forceinline__ u64t pk2(float lo, float hi) {
    u64t r; asm("mov.b64 %0, {%1,%2};" : "=l"(r) : "f"(lo), "f"(hi)); return r;
}
__device__ __forceinline__ void upk2(u64t v, float& lo, float& hi) {
    asm("mov.b64 {%0,%1}, %2;" : "=f"(lo), "=f"(hi) : "l"(v));
}
__device__ __forceinline__ u64t fma2(u64t a, u64t b, u64t c) {
    u64t d; asm("fma.rn.f32x2 %0, %1, %2, %3;" : "=l"(d) : "l"(a), "l"(b), "l"(c)); return d;
}
__device__ __forceinline__ u64t mul2(u64t a, u64t b) {
    u64t d; asm("mul.rn.f32x2 %0, %1, %2;" : "=l"(d) : "l"(a), "l"(b)); return d;
}
__device__ __forceinline__ u64t add2(u64t a, u64t b) {
    u64t d; asm("add.rn.f32x2 %0, %1, %2;" : "=l"(d) : "l"(a), "l"(b)); return d;
}

// Horizontal 11-tap blur for 2 adjacent output cols, TWO channels at once.
// Pair-interleave (A_even, A_odd, B_even, B_odd): even-k packs are adjacent
// register pairs from LDS.128 (fold free); only 5 odd-k packs/channel are real.
__device__ __forceinline__ void hblur2(const float4* __restrict__ row, int tid,
                                       const u64t* __restrict__ GWP,
                                       u64t& hA, u64t& hB)
{
    float4 q[6];
#pragma unroll
    for (int m = 0; m < 6; ++m) q[m] = row[tid + m];
    hA = mul2(GWP[0], pk2(q[0].x, q[0].y));
    hB = mul2(GWP[0], pk2(q[0].z, q[0].w));
#pragma unroll
    for (int k = 1; k < 11; ++k) {
        const int m = k >> 1;
        u64t PA = (k & 1) ? pk2(q[m].y, q[m + 1].x) : pk2(q[m].x, q[m].y);
        u64t PB = (k & 1) ? pk2(q[m].w, q[m + 1].z) : pk2(q[m].z, q[m].w);
        hA = fma2(GWP[k], PA, hA);
        hB = fma2(GWP[k], PB, hB);
    }
}

__global__ __launch_bounds__(NTHREADS, 2)
void fused_mse_ssim(const float* __restrict__ pred, const float* __restrict__ targ,
                    float* __restrict__ out)
{
    const float GW[11] = {
        0.00102838f, 0.00759876f, 0.03600077f, 0.10936070f, 0.21300554f,
        0.26601172f,
        0.21300554f, 0.10936070f, 0.03600077f, 0.00759876f, 0.00102838f
    };
    u64t GWP[11];
#pragma unroll
    for (int k = 0; k < 11; ++k) GWP[k] = pk2(GW[k], GW[k]);
    const float C1 = 1e-4f, C2 = 9e-4f;

    // Smem holds VERTICALLY-BLURRED completed rows only (2 rows/phase, dbl buf).
    // sAB[par][row][cp] = (VP0, VP1, VT0, VT1) ; sCD = (VSS0, VSS1, VDD0, VDD1)
    __shared__ float4 sAB[2][2][NCP];
    __shared__ float4 sCD[2][2][NCP];
    __shared__ float red_m[8], red_s[8];
    __shared__ unsigned s_ticket;

    const int tid = threadIdx.x;
    const int y0  = blockIdx.x * STRIP;
    const int img = blockIdx.y;

    const int n_out    = min(STRIP, OUT_H - y0);    // 28 or 26
    const int n_in     = n_out + HALO;              // 38 or 36 (always even)
    const int mse_rows = min(IMG_H - y0, (blockIdx.x == NSTRIPS - 1) ? 999 : STRIP);

    const float* __restrict__ pbase = pred + (size_t)img * (IMG_H * IMG_W);
    const float* __restrict__ tbase = targ + (size_t)img * (IMG_H * IMG_W);

    // Ring of RAW channel values (col-pair packed): 11 rows x 4 channels.
    // Row r lives in slot r % 11 (static indices via full unroll).
    u64t rgP[11], rgT[11], rgSS[11], rgDD[11];
#pragma unroll
    for (int j = 0; j < 11; ++j) { rgP[j] = rgT[j] = rgSS[j] = rgDD[j] = 0ull; }

    u64t mse2 = 0ull;
    float ssim_acc = 0.f;
    const bool emit_col = (tid <= 250);

    // Preload rows 0 and 1
    float2 pp0 = ((const float2*)(pbase + (size_t)(y0 + 0) * IMG_W))[tid];
    float2 tt0 = ((const float2*)(tbase + (size_t)(y0 + 0) * IMG_W))[tid];
    float2 pp1 = ((const float2*)(pbase + (size_t)(y0 + 1) * IMG_W))[tid];
    float2 tt1 = ((const float2*)(tbase + (size_t)(y0 + 1) * IMG_W))[tid];

    for (int rb = 0; rb < 44; rb += 22) {          // 22 ≡ 0 (mod 11)
#pragma unroll
        for (int pj = 0; pj < 11; ++pj) {
            const int r0 = rb + 2 * pj;            // even row of pair
            const int j0 = (2 * pj) % 11;          // static slot indices
            const int j1 = (2 * pj + 1) % 11;
            if (r0 < n_in) {                       // block-uniform; r1=r0+1 < n_in too
                const bool hasem = (r0 >= HALO);   // block-uniform

                // ---- insert row r0 into ring (registers only) ----
                {
                    float s0 = pp0.x + tt0.x, d0 = pp0.x - tt0.x;
                    float s1 = pp0.y + tt0.y, d1 = pp0.y - tt0.y;
                    rgP[j0]  = pk2(pp0.x, pp0.y);
                    rgT[j0]  = pk2(tt0.x, tt0.y);
                    rgSS[j0] = pk2(s0 * s0, s1 * s1);
                    u64t DD  = pk2(d0 * d0, d1 * d1);
                    rgDD[j0] = DD;
                    if (r0 < mse_rows) mse2 = add2(mse2, DD);
                }

                // ---- vertical gather for output row o0 = r0-10 (BEFORE r1
                //      insert evicts row r0-10 from the ring) ----
                u64t vb0[4];
                if (hasem) {
#pragma unroll
                    for (int i = 0; i < 11; ++i) {
                        const int sl = (j0 + 1 + i) % 11;   // row o0+i
                        if (i == 0) {
                            vb0[0] = mul2(GWP[0], rgP[sl]);
                            vb0[1] = mul2(GWP[0], rgT[sl]);
                            vb0[2] = mul2(GWP[0], rgSS[sl]);
                            vb0[3] = mul2(GWP[0], rgDD[sl]);
                        } else {
                            vb0[0] = fma2(GWP[i], rgP[sl],  vb0[0]);
                            vb0[1] = fma2(GWP[i], rgT[sl],  vb0[1]);
                            vb0[2] = fma2(GWP[i], rgSS[sl], vb0[2]);
                            vb0[3] = fma2(GWP[i], rgDD[sl], vb0[3]);
                        }
                    }
                }

                // ---- insert row r1 ----
                {
                    float s0 = pp1.x + tt1.x, d0 = pp1.x - tt1.x;
                    float s1 = pp1.y + tt1.y, d1 = pp1.y - tt1.y;
                    rgP[j1]  = pk2(pp1.x, pp1.y);
                    rgT[j1]  = pk2(tt1.x, tt1.y);
                    rgSS[j1] = pk2(s0 * s0, s1 * s1);
                    u64t DD  = pk2(d0 * d0, d1 * d1);
                    rgDD[j1] = DD;
                    if (r0 + 1 < mse_rows) mse2 = add2(mse2, DD);
                }

                // ---- prefetch next pair (registers now free; hide LDG) ----
                if (r0 + 2 < n_in) {
                    const size_t off = (size_t)(y0 + r0 + 2) * IMG_W;
                    pp0 = ((const float2*)(pbase + off))[tid];
                    tt0 = ((const float2*)(tbase + off))[tid];
                    const size_t off1 = off + IMG_W;
                    pp1 = ((const float2*)(pbase + off1))[tid];
                    tt1 = ((const float2*)(tbase + off1))[tid];
                }

                if (hasem) {
                    // ---- vertical gather for o1 = r1-10 ----
                    u64t vb1[4];
#pragma unroll
                    for (int i = 0; i < 11; ++i) {
                        const int sl = (j1 + 1 + i) % 11;
                        if (i == 0) {
                            vb1[0] = mul2(GWP[0], rgP[sl]);
                            vb1[1] = mul2(GWP[0], rgT[sl]);
                            vb1[2] = mul2(GWP[0], rgSS[sl]);
                            vb1[3] = mul2(GWP[0], rgDD[sl]);
                        } else {
                            vb1[0] = fma2(GWP[i], rgP[sl],  vb1[0]);
                            vb1[1] = fma2(GWP[i], rgT[sl],  vb1[1]);
                            vb1[2] = fma2(GWP[i], rgSS[sl], vb1[2]);
                            vb1[3] = fma2(GWP[i], rgDD[sl], vb1[3]);
                        }
                    }

                    // ---- store both vblurred rows to smem (pair-interleaved) ----
                    const int par = ((r0 - HALO) >> 1) & 1;
                    {
                        float a0, a1, b0, b1;
                        upk2(vb0[0], a0, a1); upk2(vb0[1], b0, b1);
                        sAB[par][0][tid] = make_float4(a0, a1, b0, b1);
                        upk2(vb0[2], a0, a1); upk2(vb0[3], b0, b1);
                        sCD[par][0][tid] = make_float4(a0, a1, b0, b1);
                        upk2(vb1[0], a0, a1); upk2(vb1[1], b0, b1);
                        sAB[par][1][tid] = make_float4(a0, a1, b0, b1);
                        upk2(vb1[2], a0, a1); upk2(vb1[3], b0, b1);
                        sCD[par][1][tid] = make_float4(a0, a1, b0, b1);
                    }
                    __syncthreads();

                    // ---- horizontal blur + SSIM for both completed rows ----
#pragma unroll
                    for (int rr = 0; rr < 2; ++rr) {
                        u64t M1p, M2p, BSp, BDp;
                        hblur2(sAB[par][rr], tid, GWP, M1p, M2p);
                        hblur2(sCD[par][rr], tid, GWP, BSp, BDp);
                        if (emit_col) {
                            float M1[2], M2[2], BS[2], BD[2];
                            upk2(M1p, M1[0], M1[1]);
                            upk2(M2p, M2[0], M2[1]);
                            upk2(BSp, BS[0], BS[1]);
                            upk2(BDp, BD[0], BD[1]);
#pragma unroll
                            for (int col = 0; col < 2; ++col) {
                                float m1s = M1[col] * M1[col];
                                float m2s = M2[col] * M2[col];
                                float m12 = M1[col] * M2[col];
                                float sums = m1s + m2s;
                                float sigsum = fmaf(0.5f,  BS[col] + BD[col], -sums);
                                float sig12  = fmaf(0.25f, BS[col] - BD[col], -m12);
                                float num = (2.f * m12 + C1) * (2.f * sig12 + C2);
                                float den = fmaf(sums + C1, sigsum + C2, 1e-6f);
                                ssim_acc += __fdividef(num, den);
                            }
                        }
                    }
                }
            }
        }
    }

    // Unpack packed MSE accumulator
    float mse_acc;
    {
        float mlo, mhi; upk2(mse2, mlo, mhi); mse_acc = mlo + mhi;
    }

    // Block reduction
#pragma unroll
    for (int off = 16; off > 0; off >>= 1) {
        mse_acc  += __shfl_down_sync(0xffffffffu, mse_acc,  off);
        ssim_acc += __shfl_down_sync(0xffffffffu, ssim_acc, off);
    }
    const int wrp = tid >> 5, lane = tid & 31;
    if (lane == 0) { red_m[wrp] = mse_acc; red_s[wrp] = ssim_acc; }
    __syncthreads();
    if (tid == 0) {
        float m = 0.f, s = 0.f;
#pragma unroll
        for (int w = 0; w < 8; ++w) { m += red_m[w]; s += red_s[w]; }
        const int bid = blockIdx.y * NSTRIPS + blockIdx.x;
        g_partial[bid * 2 + 0] = m;
        g_partial[bid * 2 + 1] = s;
        __threadfence();
        s_ticket = atomicAdd(&g_count, 1u);
    }
    __syncthreads();

    // Last block folds in the final reduction (no 2nd launch)
    if (s_ticket == NBLOCKS - 1) {
        __threadfence();
        double m = 0.0, s = 0.0;
        for (int i = tid; i < NBLOCKS; i += NTHREADS) {
            m += (double)g_partial[i * 2 + 0];
            s += (double)g_partial[i * 2 + 1];
        }
#pragma unroll
        for (int off = 16; off > 0; off >>= 1) {
            m += __shfl_down_sync(0xffffffffu, m, off);
            s += __shfl_down_sync(0xffffffffu, s, off);
        }
        __shared__ double sm[8], ss[8];
        if (lane == 0) { sm[wrp] = m; ss[wrp] = s; }
        __syncthreads();
        if (tid == 0) {
            double M = 0.0, S = 0.0;
#pragma unroll
            for (int w = 0; w < 8; ++w) { M += sm[w]; S += ss[w]; }
            const double mse_n  = (double)NIMG * IMG_H * IMG_W;
            const double ssim_n = (double)NIMG * OUT_H * OUT_W;
            double mse_loss  = M / mse_n;
            double ssim_loss = 1.0 - S / ssim_n;
            out[0] = (float)(0.6 * mse_loss + 0.4 * ssim_loss);
            g_count = 0;   // self-reset for next graph replay
        }
    }
}

extern "C" void kernel_launch(void* const* d_in, const int* in_sizes, int n_in,
                              void* d_out, int out_size)
{
    const float* pred = (const float*)d_in[0];
    const float* targ = (const float*)d_in[1];

    dim3 grid(NSTRIPS, NIMG, 1);   // 18 x 32 = 576 blocks
    fused_mse_ssim<<<grid, NTHREADS>>>(pred, targ, (float*)d_out);
}